// round 4
// baseline (speedup 1.0000x reference)
#include <cuda_runtime.h>
#include <cuda_bf16.h>
#include <math.h>

// ---------------------------------------------------------------------------
// DRMM matching score, GB300 (sm_103a harness, compute_103 PTX target)
// Round 4: warp-level bf16 mma.sync (HMMA.16816) with fp32 hi/lo split.
//
//   sim_T[128 d, 64 q] = A[128,160]bf16 @ B[64,160]bf16^T  (row.col mma)
//   A row = [hi_d(50) | hi_d(50) | lo_d(50) | 0(10)]
//   B row = [hi_q(50) | lo_q(50) | hi_q(50) | 0(10)]
//   dot = hi*hi + hi*lo + lo*hi  (missing lo*lo ~ 2^-16)
//   Gating branch dropped: softmax over batch sums to exactly 1.
// ---------------------------------------------------------------------------

#define BB   256
#define QQ   50
#define EE   50
#define DD   2000
#define NB   11
#define QB   (QQ * NB)        // 550
#define MT   128              // d-rows per tile
#define NTILE 16
#define ROWB 336              // smem row stride in bytes (168 bf16) — conflict-free
#define KSTEPS 10             // K=160 / 16

// smem layout (dynamic)
#define SM_B    0             // 64 * 336  = 21504
#define SM_A    21504         // 128 * 336 = 43008 -> 64512
#define SM_HIST 64512         // 550 * 4   = 2200  -> 66712
#define SM_QV   66712         // 64 ints           -> 66968
#define SM_DV   66968         // 128 ints          -> 67480
#define SM_TOTAL 67584

__device__ int g_part[NTILE * BB * QB];   // per-(tile,batch) histogram slices

// ---------------------------------------------------------------------------
__device__ __forceinline__ unsigned smem_u32(const void* p) {
    unsigned a;
    asm("{ .reg .u64 t; cvta.to.shared.u64 t, %1; cvt.u32.u64 %0, t; }"
        : "=r"(a) : "l"(p));
    return a;
}

// split fp32 pair -> packed bf16x2 (hi, lo)
__device__ __forceinline__ void split2(float x0, float x1,
                                       unsigned& hi, unsigned& lo) {
    __nv_bfloat16 h0 = __float2bfloat16(x0);
    __nv_bfloat16 h1 = __float2bfloat16(x1);
    float r0 = x0 - __bfloat162float(h0);
    float r1 = x1 - __bfloat162float(h1);
    __nv_bfloat16 l0 = __float2bfloat16(r0);
    __nv_bfloat16 l1 = __float2bfloat16(r1);
    hi = (unsigned)__bfloat16_as_ushort(h0) | ((unsigned)__bfloat16_as_ushort(h1) << 16);
    lo = (unsigned)__bfloat16_as_ushort(l0) | ((unsigned)__bfloat16_as_ushort(l1) << 16);
}

__device__ __forceinline__ void ldsm4(unsigned addr, unsigned& r0, unsigned& r1,
                                      unsigned& r2, unsigned& r3) {
    asm volatile("ldmatrix.sync.aligned.m8n8.x4.shared.b16 {%0,%1,%2,%3}, [%4];"
                 : "=r"(r0), "=r"(r1), "=r"(r2), "=r"(r3) : "r"(addr));
}

__device__ __forceinline__ void mma16816(float* c, const unsigned* a,
                                         unsigned b0, unsigned b1) {
    asm volatile(
        "mma.sync.aligned.m16n8k16.row.col.f32.bf16.bf16.f32 "
        "{%0,%1,%2,%3}, {%4,%5,%6,%7}, {%8,%9}, {%0,%1,%2,%3};"
        : "+f"(c[0]), "+f"(c[1]), "+f"(c[2]), "+f"(c[3])
        : "r"(a[0]), "r"(a[1]), "r"(a[2]), "r"(a[3]), "r"(b0), "r"(b1));
}

// ---------------------------------------------------------------------------
// Main kernel: grid (NTILE, BB), 128 threads (4 warps).
// Warp w computes d-rows [w*32, w*32+32) x all 64 q columns.
// ---------------------------------------------------------------------------
__global__ void __launch_bounds__(128)
simhist_kernel(const float* __restrict__ qemb,
               const float* __restrict__ demb,
               const int*   __restrict__ qids,
               const int*   __restrict__ dids)
{
    extern __shared__ char smem[];
    const unsigned sbase = smem_u32(smem);
    const int b    = blockIdx.y;
    const int tile = blockIdx.x;
    const int tid  = threadIdx.x;
    const int lane = tid & 31;
    const int w    = tid >> 5;

    int* hist_s = (int*)(smem + SM_HIST);
    int* qv_s   = (int*)(smem + SM_QV);
    int* dv_s   = (int*)(smem + SM_DV);

    for (int i = tid; i < QB; i += 128) hist_s[i] = 0;

    // ---- build B tile (q side): threads 0..63 own one row each ----
    if (tid < 64) {
        unsigned* brow = (unsigned*)(smem + SM_B + tid * ROWB);
        if (tid < QQ) {
            const float2* src = (const float2*)(qemb + ((size_t)b * QQ + tid) * EE);
            float2 v[25];
            float ss = 0.f;
#pragma unroll
            for (int c = 0; c < 25; c++) { v[c] = src[c]; ss += v[c].x * v[c].x + v[c].y * v[c].y; }
            const float r = 1.0f / (sqrtf(ss) + 1e-8f);
            qv_s[tid] = (qids[b * QQ + tid] > 0) ? 1 : 0;
#pragma unroll
            for (int c = 0; c < 25; c++) {
                unsigned hi, lo;
                split2(v[c].x * r, v[c].y * r, hi, lo);
                brow[c]      = hi;   // k 0..49   : hi_q
                brow[25 + c] = lo;   // k 50..99  : lo_q
                brow[50 + c] = hi;   // k 100..149: hi_q
            }
#pragma unroll
            for (int j = 75; j < 84; j++) brow[j] = 0;   // k 150..167 pad
        } else {
            qv_s[tid] = 0;
#pragma unroll
            for (int j = 0; j < 84; j++) brow[j] = 0;
        }
    }

    // ---- build A tile (d side): each thread owns one row ----
    {
        const int gd  = tile * MT + tid;
        const bool ok = (gd < DD);
        const float2* src = (const float2*)(demb + ((size_t)b * DD + (ok ? gd : 0)) * EE);
        float2 v[25];
        float ss = 0.f;
#pragma unroll
        for (int c = 0; c < 25; c++) {
            float2 x = ok ? src[c] : make_float2(0.f, 0.f);
            v[c] = x;
            ss += x.x * x.x + x.y * x.y;
        }
        const float r = 1.0f / (sqrtf(ss) + 1e-8f);
        dv_s[tid] = (ok && dids[b * DD + (ok ? gd : 0)] > 0) ? 1 : 0;

        unsigned* arow = (unsigned*)(smem + SM_A + tid * ROWB);
#pragma unroll
        for (int c = 0; c < 25; c++) {
            unsigned hi, lo;
            split2(v[c].x * r, v[c].y * r, hi, lo);
            arow[c]      = hi;   // k 0..49   : hi_d
            arow[25 + c] = hi;   // k 50..99  : hi_d
            arow[50 + c] = lo;   // k 100..149: lo_d
        }
#pragma unroll
        for (int j = 75; j < 84; j++) arow[j] = 0;
    }
    __syncthreads();

    // ---- mma mainloop ----
    float acc[2][8][4];
#pragma unroll
    for (int mt = 0; mt < 2; mt++)
#pragma unroll
        for (int nt = 0; nt < 8; nt++)
#pragma unroll
            for (int ci = 0; ci < 4; ci++) acc[mt][nt][ci] = 0.f;

    // ldmatrix lane addressing
    const unsigned aAddr = sbase + SM_A + (unsigned)(w * 32 + (lane & 15)) * ROWB
                         + (unsigned)((lane >> 4) * 16);
    const unsigned bAddr = sbase + SM_B
                         + (unsigned)((lane >> 4) * 8 + (lane & 7)) * ROWB
                         + (unsigned)(((lane >> 3) & 1) * 16);

#pragma unroll
    for (int ks = 0; ks < KSTEPS; ks++) {
        unsigned a[2][4];
        ldsm4(aAddr + ks * 32,             a[0][0], a[0][1], a[0][2], a[0][3]);
        ldsm4(aAddr + 16 * ROWB + ks * 32, a[1][0], a[1][1], a[1][2], a[1][3]);
        unsigned bq[4][4];
#pragma unroll
        for (int p = 0; p < 4; p++)
            ldsm4(bAddr + (unsigned)(p * 16 * ROWB) + ks * 32,
                  bq[p][0], bq[p][1], bq[p][2], bq[p][3]);
#pragma unroll
        for (int mt = 0; mt < 2; mt++)
#pragma unroll
            for (int p = 0; p < 4; p++) {
                mma16816(acc[mt][2 * p],     a[mt], bq[p][0], bq[p][1]);
                mma16816(acc[mt][2 * p + 1], a[mt], bq[p][2], bq[p][3]);
            }
    }

    // ---- epilogue: bin + warp-aggregated histogram atomics ----
    const int rbase = w * 32 + (lane >> 2);
    const int cbase = (lane & 3) * 2;
#pragma unroll
    for (int mt = 0; mt < 2; mt++)
#pragma unroll
        for (int nt = 0; nt < 8; nt++)
#pragma unroll
            for (int ci = 0; ci < 4; ci++) {
                const int q = nt * 8 + cbase + (ci & 1);
                const int r = rbase + mt * 16 + ((ci >> 1) << 3);
                const bool val = dv_s[r] && qv_s[q];
                float sim = acc[mt][nt][ci];
                int bin = (int)((sim + 1.000001f) * 5.0f);
                bin = min(max(bin, 0), NB - 1);
                const int key = val ? (q * NB + bin) : (600 + lane);
                unsigned m = __match_any_sync(0xffffffffu, key);
                if (val && lane == (int)(__ffs(m) - 1))
                    atomicAdd(&hist_s[key], (int)__popc(m));
            }

    __syncthreads();
    int* dst = g_part + ((size_t)tile * BB + b) * QB;
    for (int i = tid; i < QB; i += 128) dst[i] = hist_s[i];
}

// ---------------------------------------------------------------------------
// Reduce: out[b] = b1 + sum_i log(sum_tiles hist + 1e-5) * W1[i]
// ---------------------------------------------------------------------------
__global__ void reduce_kernel(const float* __restrict__ W1,
                              const float* __restrict__ b1,
                              float* __restrict__ out)
{
    const int b = blockIdx.x;
    const int t = threadIdx.x;
    float p = 0.f;
    for (int i = t; i < QB; i += 256) {
        int h = 0;
#pragma unroll
        for (int s = 0; s < NTILE; s++)
            h += g_part[((size_t)s * BB + b) * QB + i];
        p += logf((float)h + 1e-5f) * W1[i];
    }
#pragma unroll
    for (int o = 16; o > 0; o >>= 1) p += __shfl_down_sync(0xffffffffu, p, o);

    __shared__ float red[8];
    if ((t & 31) == 0) red[t >> 5] = p;
    __syncthreads();
    if (t == 0) {
        float s = 0.f;
#pragma unroll
        for (int i = 0; i < 8; i++) s += red[i];
        out[b] = s + b1[0];
    }
}

// ---------------------------------------------------------------------------
extern "C" void kernel_launch(void* const* d_in, const int* in_sizes, int n_in,
                              void* d_out, int out_size)
{
    const float* qemb = (const float*)d_in[0];
    const float* demb = (const float*)d_in[1];
    const float* W1   = (const float*)d_in[2];
    const float* b1   = (const float*)d_in[3];
    const int*   qids = (const int*)d_in[5];
    const int*   dids = (const int*)d_in[6];
    for (int i = 0; i < n_in; i++) {
        switch (in_sizes[i]) {
            case BB * QQ * EE:  qemb = (const float*)d_in[i]; break;
            case BB * DD * EE:  demb = (const float*)d_in[i]; break;
            case QB:            W1   = (const float*)d_in[i]; break;
            case 1:             b1   = (const float*)d_in[i]; break;
            case BB * QQ:       qids = (const int*)d_in[i];   break;
            case BB * DD:       dids = (const int*)d_in[i];   break;
            default: break;     // Wg unused (softmax over batch sums to 1)
        }
    }
    float* out = (float*)d_out;

    static int smem_set = 0;
    if (!smem_set) {
        cudaFuncSetAttribute(simhist_kernel,
                             cudaFuncAttributeMaxDynamicSharedMemorySize, SM_TOTAL);
        smem_set = 1;
    }

    dim3 grid(NTILE, BB);                         // (16, 256)
    simhist_kernel<<<grid, 128, SM_TOTAL>>>(qemb, demb, qids, dids);
    reduce_kernel<<<BB, 256>>>(W1, b1, out);
}

// round 5
// speedup vs baseline: 1.4887x; 1.4887x over previous
#include <cuda_runtime.h>
#include <math.h>

// ---------------------------------------------------------------------------
// DRMM matching score, GB300 (sm_103a) — round 5: packed fp32 FFMA2, no spill
//   * fma.rn.f32x2 halves fp32 instruction count (ptxas never emits it from C++)
//   * 128 threads x 2 d-rows/thread, __launch_bounds__(128,3): ~135 regs, no spill
//   * q rows pre-normalized in smem; d rows pre-scaled in registers ->
//     epilogue needs no norm multiplies
//   * ld.shared.v4 broadcast q loads (4 elems / LDS)
//   * gating branch dropped: softmax over batch sums to exactly 1
// ---------------------------------------------------------------------------

#define BB   256
#define QQ   50
#define EE   50
#define DD   2000
#define NB   11
#define QB   (QQ * NB)        // 550
#define NTHREADS 128
#define TROWS 256             // d-rows per CTA (2 per thread)
#define NTILE 8               // 8*256 = 2048 >= 2000
#define QROW 52               // padded floats per q row (13 float4)

__device__ int g_part[NTILE * BB * QB];   // per-(tile,batch) histogram slices

typedef unsigned long long u64;

__device__ __forceinline__ u64 pack2(float x, float y) {
    u64 r; asm("mov.b64 %0, {%1, %2};" : "=l"(r) : "f"(x), "f"(y)); return r;
}
__device__ __forceinline__ float2 unpack2(u64 v) {
    float2 r; asm("mov.b64 {%0, %1}, %2;" : "=f"(r.x), "=f"(r.y) : "l"(v)); return r;
}
__device__ __forceinline__ void ffma2(u64& d, u64 a, u64 b) {
    asm("fma.rn.f32x2 %0, %1, %2, %0;" : "+l"(d) : "l"(a), "l"(b));
}
__device__ __forceinline__ void mulf2(u64& d, u64 a) {
    asm("mul.rn.f32x2 %0, %0, %1;" : "+l"(d) : "l"(a));
}
__device__ __forceinline__ u64 addf2(u64 a, u64 b) {
    u64 r; asm("add.rn.f32x2 %0, %1, %2;" : "=l"(r) : "l"(a), "l"(b)); return r;
}

// ---------------------------------------------------------------------------
// Main kernel: grid (NTILE, BB), 128 threads. Thread owns d-rows (t, t+128).
// ---------------------------------------------------------------------------
__global__ void __launch_bounds__(NTHREADS, 3)
simhist_kernel(const float* __restrict__ qemb,
               const float* __restrict__ demb,
               const int*   __restrict__ qids,
               const int*   __restrict__ dids)
{
    __shared__ float qs[QQ * QROW];     // normalized q rows (padded, float4 rows)
    __shared__ int   hist_s[QB];
    __shared__ int   qv_s[QQ];

    const int b    = blockIdx.y;
    const int tile = blockIdx.x;
    const int t    = threadIdx.x;
    const int lane = t & 31;

    // ---- stage raw q tile (float2 rows, stride 26 float2) ----
    {
        const float2* qsrc = (const float2*)(qemb + (size_t)b * QQ * EE);
        for (int i = t; i < QQ * 25; i += NTHREADS)
            ((float2*)qs)[(i / 25) * 26 + (i % 25)] = qsrc[i];
        for (int i = t; i < QB; i += NTHREADS) hist_s[i] = 0;
    }

    // ---- load this thread's 2 d-rows, pack, accumulate sumsq ----
    const int dA = tile * TROWS + t;
    const int dB = dA + NTHREADS;
    const bool okA = (dA < DD);
    const bool okB = (dB < DD);
    u64 a0[26], a1[26];
    {
        const float2* pA = (const float2*)(demb + ((size_t)b * DD + (okA ? dA : 0)) * EE);
        const float2* pB = (const float2*)(demb + ((size_t)b * DD + (okB ? dB : 0)) * EE);
        float ssA = 0.f, ssB = 0.f;
#pragma unroll
        for (int c = 0; c < 25; c++) {
            float2 v = okA ? pA[c] : make_float2(0.f, 0.f);
            ssA += v.x * v.x + v.y * v.y;
            a0[c] = pack2(v.x, v.y);
            float2 w = okB ? pB[c] : make_float2(0.f, 0.f);
            ssB += w.x * w.x + w.y * w.y;
            a1[c] = pack2(w.x, w.y);
        }
        a0[25] = 0ull; a1[25] = 0ull;
        const float rA = 1.0f / (sqrtf(ssA) + 1e-8f);
        const float rB = 1.0f / (sqrtf(ssB) + 1e-8f);
        const u64 prA = pack2(rA, rA);
        const u64 prB = pack2(rB, rB);
#pragma unroll
        for (int c = 0; c < 25; c++) { mulf2(a0[c], prA); mulf2(a1[c], prB); }
    }
    const bool addA = okA && (dids[b * DD + (okA ? dA : 0)] > 0);
    const bool addB = okB && (dids[b * DD + (okB ? dB : 0)] > 0);
    const unsigned vbA = __ballot_sync(0xffffffffu, addA);
    const unsigned vbB = __ballot_sync(0xffffffffu, addB);

    __syncthreads();

    // ---- normalize q rows in place (threads 0..49), zero pad, validity ----
    if (t < QQ) {
        float* r = &qs[t * QROW];
        float ss = 0.f;
#pragma unroll
        for (int e = 0; e < EE; e++) ss += r[e] * r[e];
        const float rq = 1.0f / (sqrtf(ss) + 1e-8f);
#pragma unroll
        for (int e = 0; e < EE; e++) r[e] *= rq;
        r[50] = 0.f; r[51] = 0.f;
        qv_s[t] = (qids[b * QQ + t] > 0) ? 1 : 0;
    }
    __syncthreads();

    // ---- mainloop: 4 independent FFMA2 chains per q ----
    for (int q = 0; q < QQ; q++) {
        if (!qv_s[q]) continue;                  // uniform branch
        const float4* w = (const float4*)&qs[q * QROW];
        u64 s0a = 0ull, s0b = 0ull, s1a = 0ull, s1b = 0ull;
#pragma unroll
        for (int c4 = 0; c4 < 13; c4++) {
            float4 wv = w[c4];                   // broadcast LDS.128
            u64 w01 = pack2(wv.x, wv.y);
            u64 w23 = pack2(wv.z, wv.w);
            ffma2(s0a, a0[2 * c4],     w01);
            ffma2(s0b, a0[2 * c4 + 1], w23);
            ffma2(s1a, a1[2 * c4],     w01);
            ffma2(s1b, a1[2 * c4 + 1], w23);
        }
        const int base = q * NB;

        float2 uA = unpack2(addf2(s0a, s0b));
        float simA = uA.x + uA.y;
        int binA = (int)fmaf(simA, 5.0f, 5.000005f);
        binA = min(max(binA, 0), NB - 1);
        unsigned mA = __match_any_sync(0xffffffffu, binA) & vbA;
        if (addA && lane == (int)(__ffs(mA) - 1))
            atomicAdd(&hist_s[base + binA], (int)__popc(mA));

        float2 uB = unpack2(addf2(s1a, s1b));
        float simB = uB.x + uB.y;
        int binB = (int)fmaf(simB, 5.0f, 5.000005f);
        binB = min(max(binB, 0), NB - 1);
        unsigned mB = __match_any_sync(0xffffffffu, binB) & vbB;
        if (addB && lane == (int)(__ffs(mB) - 1))
            atomicAdd(&hist_s[base + binB], (int)__popc(mB));
    }

    __syncthreads();
    int* dst = g_part + ((size_t)tile * BB + b) * QB;
    for (int i = t; i < QB; i += NTHREADS) dst[i] = hist_s[i];
}

// ---------------------------------------------------------------------------
// Reduce: out[b] = b1 + sum_i log(sum_tiles hist + 1e-5) * W1[i]
// ---------------------------------------------------------------------------
__global__ void reduce_kernel(const float* __restrict__ W1,
                              const float* __restrict__ b1,
                              float* __restrict__ out)
{
    const int b = blockIdx.x;
    const int t = threadIdx.x;
    float p = 0.f;
    for (int i = t; i < QB; i += 256) {
        int h = 0;
#pragma unroll
        for (int s = 0; s < NTILE; s++)
            h += g_part[((size_t)s * BB + b) * QB + i];
        p += logf((float)h + 1e-5f) * W1[i];
    }
#pragma unroll
    for (int o = 16; o > 0; o >>= 1) p += __shfl_down_sync(0xffffffffu, p, o);

    __shared__ float red[8];
    if ((t & 31) == 0) red[t >> 5] = p;
    __syncthreads();
    if (t == 0) {
        float s = 0.f;
#pragma unroll
        for (int i = 0; i < 8; i++) s += red[i];
        out[b] = s + b1[0];
    }
}

// ---------------------------------------------------------------------------
extern "C" void kernel_launch(void* const* d_in, const int* in_sizes, int n_in,
                              void* d_out, int out_size)
{
    const float* qemb = (const float*)d_in[0];
    const float* demb = (const float*)d_in[1];
    const float* W1   = (const float*)d_in[2];
    const float* b1   = (const float*)d_in[3];
    const int*   qids = (const int*)d_in[5];
    const int*   dids = (const int*)d_in[6];
    for (int i = 0; i < n_in; i++) {
        switch (in_sizes[i]) {
            case BB * QQ * EE:  qemb = (const float*)d_in[i]; break;
            case BB * DD * EE:  demb = (const float*)d_in[i]; break;
            case QB:            W1   = (const float*)d_in[i]; break;
            case 1:             b1   = (const float*)d_in[i]; break;
            case BB * QQ:       qids = (const int*)d_in[i];   break;
            case BB * DD:       dids = (const int*)d_in[i];   break;
            default: break;     // Wg unused (softmax over batch sums to 1)
        }
    }
    float* out = (float*)d_out;

    dim3 grid(NTILE, BB);                         // (8, 256) = 2048 CTAs
    simhist_kernel<<<grid, NTHREADS>>>(qemb, demb, qids, dids);
    reduce_kernel<<<BB, 256>>>(W1, b1, out);
}